// round 4
// baseline (speedup 1.0000x reference)
#include <cuda_runtime.h>

#define NCH   192
#define WSTR  64
#define N4    3145728   // 12,582,912 floats / 4

// Precomputed per-channel weights: softplus(mats), biases, tanh(factors).
// Layout per channel (stride 64):
//  [0:3)  sp_m0, [3:12) sp_m1, [12:21) sp_m2, [21:30) sp_m3, [30:33) sp_m4
//  [33:36) b0, [36:39) b1, [39:42) b2, [42:45) b3, [45] b4
//  [46:49) tf0, [49:52) tf1, [52:55) tf2, [55:58) tf3
__device__ float g_w[NCH * WSTR];

__global__ void prep_kernel(
    const float* __restrict__ m0, const float* __restrict__ m1,
    const float* __restrict__ m2, const float* __restrict__ m3,
    const float* __restrict__ m4,
    const float* __restrict__ b0, const float* __restrict__ b1,
    const float* __restrict__ b2, const float* __restrict__ b3,
    const float* __restrict__ b4,
    const float* __restrict__ f0, const float* __restrict__ f1,
    const float* __restrict__ f2, const float* __restrict__ f3)
{
    int c = threadIdx.x;
    if (c >= NCH) return;
    float* W = g_w + c * WSTR;
#pragma unroll
    for (int j = 0; j < 3; j++) W[0  + j] = log1pf(expf(m0[c*3 + j]));
#pragma unroll
    for (int j = 0; j < 9; j++) W[3  + j] = log1pf(expf(m1[c*9 + j]));
#pragma unroll
    for (int j = 0; j < 9; j++) W[12 + j] = log1pf(expf(m2[c*9 + j]));
#pragma unroll
    for (int j = 0; j < 9; j++) W[21 + j] = log1pf(expf(m3[c*9 + j]));
#pragma unroll
    for (int j = 0; j < 3; j++) W[30 + j] = log1pf(expf(m4[c*3 + j]));
#pragma unroll
    for (int j = 0; j < 3; j++) {
        W[33 + j] = b0[c*3 + j];
        W[36 + j] = b1[c*3 + j];
        W[39 + j] = b2[c*3 + j];
        W[42 + j] = b3[c*3 + j];
    }
    W[45] = b4[c];
#pragma unroll
    for (int j = 0; j < 3; j++) {
        W[46 + j] = tanhf(f0[c*3 + j]);
        W[49 + j] = tanhf(f1[c*3 + j]);
        W[52 + j] = tanhf(f2[c*3 + j]);
        W[55 + j] = tanhf(f3[c*3 + j]);
    }
}

// MUFU.TANH — single-instruction tanh approximation. Only used on the gate
// path where the result is scaled by tanh(factor) ~ 0.01, so its ~6e-4 abs
// error contributes < 1e-5 to the logits.
__device__ __forceinline__ float tanha(float x) {
    float y;
    asm("tanh.approx.f32 %0, %1;" : "=f"(y) : "f"(x));
    return y;
}

__device__ __forceinline__ float rcpa(float x) {
    float y;
    asm("rcp.approx.f32 %0, %1;" : "=f"(y) : "f"(x));
    return y;
}

// Accurate sigmoid (EX2-based __expf ~2 ulp + rcp.approx ~2^-22): used on the
// final likelihood path where precision matters directly.
__device__ __forceinline__ float sigm(float z) {
    return rcpa(1.0f + __expf(-z));
}

__device__ __forceinline__ float eval_mlp(float v, const float* W) {
    float a0 = fmaf(W[0], v, W[33]);
    float a1 = fmaf(W[1], v, W[34]);
    float a2 = fmaf(W[2], v, W[35]);
    a0 = fmaf(W[46], tanha(a0), a0);
    a1 = fmaf(W[47], tanha(a1), a1);
    a2 = fmaf(W[48], tanha(a2), a2);
#pragma unroll
    for (int L = 0; L < 3; L++) {
        const int mo = 3 + L*9, bo = 36 + L*3, fo = 49 + L*3;
        float n0 = fmaf(W[mo+0], a0, fmaf(W[mo+1], a1, fmaf(W[mo+2], a2, W[bo+0])));
        float n1 = fmaf(W[mo+3], a0, fmaf(W[mo+4], a1, fmaf(W[mo+5], a2, W[bo+1])));
        float n2 = fmaf(W[mo+6], a0, fmaf(W[mo+7], a1, fmaf(W[mo+8], a2, W[bo+2])));
        a0 = fmaf(W[fo+0], tanha(n0), n0);
        a1 = fmaf(W[fo+1], tanha(n1), n1);
        a2 = fmaf(W[fo+2], tanha(n2), n2);
    }
    return fmaf(W[30], a0, fmaf(W[31], a1, fmaf(W[32], a2, W[45])));
}

__device__ __forceinline__ void do_elem(float xx, float nn, float& o, float& l,
                                        const float* W) {
    float u = xx + nn;
    o = u;
    float lo = eval_mlp(u - 0.5f, W);
    float up = eval_mlp(u + 0.5f, W);
    // sign = -sign(lower + upper); picks the numerically stable branch
    float s  = lo + up;
    float sg = (s > 0.0f) ? -1.0f : ((s < 0.0f) ? 1.0f : 0.0f);
    float like = fabsf(sigm(sg * up) - sigm(sg * lo));
    l = fmaxf(like, 1e-9f);
}

__global__ void __launch_bounds__(256)
eb_kernel(const float4* __restrict__ x, const float4* __restrict__ nz,
          float4* __restrict__ out)
{
    int slab = blockIdx.x;        // b*C + c  (0..3071), each slab = 4096 elems
    int c = slab % NCH;

    const float* Wg = g_w + c * WSTR;
    float W[58];
#pragma unroll
    for (int i = 0; i < 58; i++) W[i] = Wg[i];

    int base = slab * 1024;       // float4 units
#pragma unroll 1
    for (int k = 0; k < 4; k++) {
        int i4 = base + (int)threadIdx.x + k * 256;
        float4 xv = x[i4];
        float4 nv = nz[i4];
        float4 ov, lv;
        do_elem(xv.x, nv.x, ov.x, lv.x, W);
        do_elem(xv.y, nv.y, ov.y, lv.y, W);
        do_elem(xv.z, nv.z, ov.z, lv.z, W);
        do_elem(xv.w, nv.w, ov.w, lv.w, W);
        out[i4]      = ov;   // outputs = x + noise
        out[N4 + i4] = lv;   // likelihood
    }
}

extern "C" void kernel_launch(void* const* d_in, const int* in_sizes, int n_in,
                              void* d_out, int out_size)
{
    const float* x  = (const float*)d_in[0];
    const float* nz = (const float*)d_in[1];
    const float *m[5], *b[5], *f[4];

    // Two possible metadata orders:
    //  signature order:  x, noise, m0..m4, b0..b4, f0..f3  -> in_sizes[3]=1728 (m1)
    //  dict order:       x, noise, m0,b0,f0, m1,b1,f1, ...  -> in_sizes[3]=576  (b0)
    if (n_in >= 16 && in_sizes[3] == 1728) {
        for (int i = 0; i < 5; i++) m[i] = (const float*)d_in[2 + i];
        for (int i = 0; i < 5; i++) b[i] = (const float*)d_in[7 + i];
        for (int i = 0; i < 4; i++) f[i] = (const float*)d_in[12 + i];
    } else {
        int idx = 2;
        for (int i = 0; i < 5; i++) {
            m[i] = (const float*)d_in[idx++];
            b[i] = (const float*)d_in[idx++];
            if (i < 4) f[i] = (const float*)d_in[idx++];
        }
    }

    prep_kernel<<<1, 192>>>(m[0], m[1], m[2], m[3], m[4],
                            b[0], b[1], b[2], b[3], b[4],
                            f[0], f[1], f[2], f[3]);
    eb_kernel<<<3072, 256>>>((const float4*)x, (const float4*)nz, (float4*)d_out);
}

// round 12
// speedup vs baseline: 2.1088x; 2.1088x over previous
#include <cuda_runtime.h>

#define NCH    192
#define LUT_N  2048
#define LUT_LO 16.0f      // LUT covers u in [-16, +16)
#define LUT_SC 64.0f      // entries per unit u  (spacing 1/64)
#define N4     3145728    // 12,582,912 floats / 4

// Per-channel likelihood lookup table, built once per launch.
__device__ float g_lut[NCH * LUT_N];

__device__ __forceinline__ float tanha(float x) {
    float y; asm("tanh.approx.f32 %0, %1;" : "=f"(y) : "f"(x)); return y;
}
__device__ __forceinline__ float rcpa(float x) {
    float y; asm("rcp.approx.f32 %0, %1;" : "=f"(y) : "f"(x)); return y;
}
// Accurate sigmoid for the final likelihood path (EX2-based exp + rcp).
__device__ __forceinline__ float sigm(float z) {
    return rcpa(1.0f + __expf(-z));
}

// W layout: [0:3) m0, [3:12) m1, [12:21) m2, [21:30) m3, [30:33) m4,
//           [33:36) b0, [36:39) b1, [39:42) b2, [42:45) b3, [45] b4,
//           [46:49) tf0, [49:52) tf1, [52:55) tf2, [55:58) tf3
__device__ __forceinline__ float eval_mlp(float v, const float* W) {
    float a0 = fmaf(W[0], v, W[33]);
    float a1 = fmaf(W[1], v, W[34]);
    float a2 = fmaf(W[2], v, W[35]);
    a0 = fmaf(W[46], tanha(a0), a0);
    a1 = fmaf(W[47], tanha(a1), a1);
    a2 = fmaf(W[48], tanha(a2), a2);
#pragma unroll
    for (int L = 0; L < 3; L++) {
        const int mo = 3 + L*9, bo = 36 + L*3, fo = 49 + L*3;
        float n0 = fmaf(W[mo+0], a0, fmaf(W[mo+1], a1, fmaf(W[mo+2], a2, W[bo+0])));
        float n1 = fmaf(W[mo+3], a0, fmaf(W[mo+4], a1, fmaf(W[mo+5], a2, W[bo+1])));
        float n2 = fmaf(W[mo+6], a0, fmaf(W[mo+7], a1, fmaf(W[mo+8], a2, W[bo+2])));
        a0 = fmaf(W[fo+0], tanha(n0), n0);
        a1 = fmaf(W[fo+1], tanha(n1), n1);
        a2 = fmaf(W[fo+2], tanha(n2), n2);
    }
    return fmaf(W[30], a0, fmaf(W[31], a1, fmaf(W[32], a2, W[45])));
}

// Build the per-channel likelihood LUT. grid=(LUT_N/256, NCH), block=256.
// Threads 0..57 prep (softplus / tanh) the channel weights into smem first.
__global__ void __launch_bounds__(256) build_kernel(
    const float* __restrict__ m0, const float* __restrict__ m1,
    const float* __restrict__ m2, const float* __restrict__ m3,
    const float* __restrict__ m4,
    const float* __restrict__ b0, const float* __restrict__ b1,
    const float* __restrict__ b2, const float* __restrict__ b3,
    const float* __restrict__ b4,
    const float* __restrict__ f0, const float* __restrict__ f1,
    const float* __restrict__ f2, const float* __restrict__ f3)
{
    __shared__ float W[58];
    int c = blockIdx.y;
    int t = threadIdx.x;
    if (t < 58) {
        int s = t;
        float val;
        if      (s <  3) val = log1pf(expf(m0[c*3 + s      ]));
        else if (s < 12) val = log1pf(expf(m1[c*9 + s -  3 ]));
        else if (s < 21) val = log1pf(expf(m2[c*9 + s - 12 ]));
        else if (s < 30) val = log1pf(expf(m3[c*9 + s - 21 ]));
        else if (s < 33) val = log1pf(expf(m4[c*3 + s - 30 ]));
        else if (s < 36) val = b0[c*3 + s - 33];
        else if (s < 39) val = b1[c*3 + s - 36];
        else if (s < 42) val = b2[c*3 + s - 39];
        else if (s < 45) val = b3[c*3 + s - 42];
        else if (s < 46) val = b4[c];
        else if (s < 49) val = tanhf(f0[c*3 + s - 46]);
        else if (s < 52) val = tanhf(f1[c*3 + s - 49]);
        else if (s < 55) val = tanhf(f2[c*3 + s - 52]);
        else             val = tanhf(f3[c*3 + s - 55]);
        W[s] = val;
    }
    __syncthreads();

    int p = blockIdx.x * 256 + t;                 // 0 .. LUT_N-1
    float u  = fmaf((float)p, 1.0f / LUT_SC, -LUT_LO);
    float lo = eval_mlp(u - 0.5f, W);
    float up = eval_mlp(u + 0.5f, W);
    float sum = lo + up;
    float sg  = (sum > 0.0f) ? -1.0f : ((sum < 0.0f) ? 1.0f : 0.0f);
    float like = fabsf(sigm(sg * up) - sigm(sg * lo));
    g_lut[c * LUT_N + p] = fmaxf(like, 1e-9f);
}

__device__ __forceinline__ float lut_interp(float u, const float* lut) {
    float tt = fmaf(u, LUT_SC, LUT_LO * LUT_SC);       // (u + 16) * 64
    tt = fminf(fmaxf(tt, 0.0f), (float)(LUT_N - 2) + 0.999f);
    int   i  = (int)tt;
    float fr = tt - (float)i;
    float a = lut[i];
    float b = lut[i + 1];
    return fmaf(fr, b - a, a);
}

// Main streaming kernel: block per (b,c) slab of 4096 elements.
__global__ void __launch_bounds__(256)
eb_main(const float4* __restrict__ x, const float4* __restrict__ nz,
        float4* __restrict__ out)
{
    __shared__ float lut[LUT_N];
    int slab = blockIdx.x;            // b*192 + c
    int c = slab % NCH;

    // Stage this channel's LUT (8 KB) into shared memory.
    const float4* src = (const float4*)(g_lut + c * LUT_N);
    float4* dst = (float4*)lut;
#pragma unroll
    for (int i = 0; i < 2; i++)
        dst[threadIdx.x + i * 256] = src[threadIdx.x + i * 256];
    __syncthreads();

    int base = slab * 1024;           // float4 units
#pragma unroll
    for (int k = 0; k < 4; k++) {
        int i4 = base + (int)threadIdx.x + k * 256;
        float4 xv = x[i4];
        float4 nv = nz[i4];
        float4 ov, lv;
        ov.x = xv.x + nv.x;  lv.x = lut_interp(ov.x, lut);
        ov.y = xv.y + nv.y;  lv.y = lut_interp(ov.y, lut);
        ov.z = xv.z + nv.z;  lv.z = lut_interp(ov.z, lut);
        ov.w = xv.w + nv.w;  lv.w = lut_interp(ov.w, lut);
        out[i4]      = ov;   // outputs = x + noise
        out[N4 + i4] = lv;   // likelihood
    }
}

extern "C" void kernel_launch(void* const* d_in, const int* in_sizes, int n_in,
                              void* d_out, int out_size)
{
    const float* x  = (const float*)d_in[0];
    const float* nz = (const float*)d_in[1];
    const float *m[5], *b[5], *f[4];

    // Two possible metadata orders:
    //  signature order:  x, noise, m0..m4, b0..b4, f0..f3  -> in_sizes[3]=1728 (m1)
    //  dict order:       x, noise, m0,b0,f0, m1,b1,f1, ...  -> in_sizes[3]=576  (b0)
    if (n_in >= 16 && in_sizes[3] == 1728) {
        for (int i = 0; i < 5; i++) m[i] = (const float*)d_in[2 + i];
        for (int i = 0; i < 5; i++) b[i] = (const float*)d_in[7 + i];
        for (int i = 0; i < 4; i++) f[i] = (const float*)d_in[12 + i];
    } else {
        int idx = 2;
        for (int i = 0; i < 5; i++) {
            m[i] = (const float*)d_in[idx++];
            b[i] = (const float*)d_in[idx++];
            if (i < 4) f[i] = (const float*)d_in[idx++];
        }
    }

    dim3 bgrid(LUT_N / 256, NCH);
    build_kernel<<<bgrid, 256>>>(m[0], m[1], m[2], m[3], m[4],
                                 b[0], b[1], b[2], b[3], b[4],
                                 f[0], f[1], f[2], f[3]);
    eb_main<<<3072, 256>>>((const float4*)x, (const float4*)nz, (float4*)d_out);
}

// round 16
// speedup vs baseline: 2.1118x; 1.0015x over previous
#include <cuda_runtime.h>

#define NCH    192
#define LUT_N  2048
#define LUT_LO 16.0f      // LUT covers u in [-16, +16)
#define LUT_SC 64.0f      // entries per unit u  (spacing 1/64)
#define N4     3145728    // 12,582,912 floats / 4

// Per-channel likelihood lookup table, built once per launch.
__device__ float g_lut[NCH * LUT_N];

__device__ __forceinline__ float tanha(float x) {
    float y; asm("tanh.approx.f32 %0, %1;" : "=f"(y) : "f"(x)); return y;
}
__device__ __forceinline__ float rcpa(float x) {
    float y; asm("rcp.approx.f32 %0, %1;" : "=f"(y) : "f"(x)); return y;
}
// Accurate sigmoid for the final likelihood path (EX2-based exp + rcp).
__device__ __forceinline__ float sigm(float z) {
    return rcpa(1.0f + __expf(-z));
}

// W layout: [0:3) m0, [3:12) m1, [12:21) m2, [21:30) m3, [30:33) m4,
//           [33:36) b0, [36:39) b1, [39:42) b2, [42:45) b3, [45] b4,
//           [46:49) tf0, [49:52) tf1, [52:55) tf2, [55:58) tf3
__device__ __forceinline__ float eval_mlp(float v, const float* W) {
    float a0 = fmaf(W[0], v, W[33]);
    float a1 = fmaf(W[1], v, W[34]);
    float a2 = fmaf(W[2], v, W[35]);
    a0 = fmaf(W[46], tanha(a0), a0);
    a1 = fmaf(W[47], tanha(a1), a1);
    a2 = fmaf(W[48], tanha(a2), a2);
#pragma unroll
    for (int L = 0; L < 3; L++) {
        const int mo = 3 + L*9, bo = 36 + L*3, fo = 49 + L*3;
        float n0 = fmaf(W[mo+0], a0, fmaf(W[mo+1], a1, fmaf(W[mo+2], a2, W[bo+0])));
        float n1 = fmaf(W[mo+3], a0, fmaf(W[mo+4], a1, fmaf(W[mo+5], a2, W[bo+1])));
        float n2 = fmaf(W[mo+6], a0, fmaf(W[mo+7], a1, fmaf(W[mo+8], a2, W[bo+2])));
        a0 = fmaf(W[fo+0], tanha(n0), n0);
        a1 = fmaf(W[fo+1], tanha(n1), n1);
        a2 = fmaf(W[fo+2], tanha(n2), n2);
    }
    return fmaf(W[30], a0, fmaf(W[31], a1, fmaf(W[32], a2, W[45])));
}

// Build the per-channel likelihood LUT. grid=(LUT_N/256, NCH), block=256.
// Threads 0..57 prep (softplus / tanh) the channel weights into smem first.
__global__ void __launch_bounds__(256) build_kernel(
    const float* __restrict__ m0, const float* __restrict__ m1,
    const float* __restrict__ m2, const float* __restrict__ m3,
    const float* __restrict__ m4,
    const float* __restrict__ b0, const float* __restrict__ b1,
    const float* __restrict__ b2, const float* __restrict__ b3,
    const float* __restrict__ b4,
    const float* __restrict__ f0, const float* __restrict__ f1,
    const float* __restrict__ f2, const float* __restrict__ f3)
{
    __shared__ float W[58];
    int c = blockIdx.y;
    int t = threadIdx.x;
    if (t < 58) {
        int s = t;
        float val;
        if      (s <  3) val = log1pf(expf(m0[c*3 + s      ]));
        else if (s < 12) val = log1pf(expf(m1[c*9 + s -  3 ]));
        else if (s < 21) val = log1pf(expf(m2[c*9 + s - 12 ]));
        else if (s < 30) val = log1pf(expf(m3[c*9 + s - 21 ]));
        else if (s < 33) val = log1pf(expf(m4[c*3 + s - 30 ]));
        else if (s < 36) val = b0[c*3 + s - 33];
        else if (s < 39) val = b1[c*3 + s - 36];
        else if (s < 42) val = b2[c*3 + s - 39];
        else if (s < 45) val = b3[c*3 + s - 42];
        else if (s < 46) val = b4[c];
        else if (s < 49) val = tanhf(f0[c*3 + s - 46]);
        else if (s < 52) val = tanhf(f1[c*3 + s - 49]);
        else if (s < 55) val = tanhf(f2[c*3 + s - 52]);
        else             val = tanhf(f3[c*3 + s - 55]);
        W[s] = val;
    }
    __syncthreads();

    int p = blockIdx.x * 256 + t;                 // 0 .. LUT_N-1
    float u  = fmaf((float)p, 1.0f / LUT_SC, -LUT_LO);
    float lo = eval_mlp(u - 0.5f, W);
    float up = eval_mlp(u + 0.5f, W);
    float sum = lo + up;
    float sg  = (sum > 0.0f) ? -1.0f : ((sum < 0.0f) ? 1.0f : 0.0f);
    float like = fabsf(sigm(sg * up) - sigm(sg * lo));
    g_lut[c * LUT_N + p] = fmaxf(like, 1e-9f);
}

__device__ __forceinline__ float lut_interp(float u, const float* lut) {
    float tt = fmaf(u, LUT_SC, LUT_LO * LUT_SC);       // (u + 16) * 64
    tt = fminf(fmaxf(tt, 0.0f), (float)(LUT_N - 2) + 0.999f);
    int   i  = (int)tt;
    float fr = tt - (float)i;
    float a = lut[i];
    float b = lut[i + 1];
    return fmaf(fr, b - a, a);
}

// Main streaming kernel: block per (b,c) slab of 4096 elements.
// All 8 global loads are front-batched per thread to maximize MLP,
// so DRAM latency is covered by outstanding loads instead of re-exposed
// every loop iteration.
__global__ void __launch_bounds__(256)
eb_main(const float4* __restrict__ x, const float4* __restrict__ nz,
        float4* __restrict__ out)
{
    __shared__ float lut[LUT_N];
    int slab = blockIdx.x;            // b*192 + c
    int c = slab % NCH;

    // Stage this channel's LUT (8 KB) into shared memory.
    const float4* src = (const float4*)(g_lut + c * LUT_N);
    float4* dst = (float4*)lut;
#pragma unroll
    for (int i = 0; i < 2; i++)
        dst[threadIdx.x + i * 256] = src[threadIdx.x + i * 256];
    __syncthreads();

    int base = slab * 1024 + (int)threadIdx.x;   // float4 units

    float4 xv[4], nv[4];
#pragma unroll
    for (int k = 0; k < 4; k++) xv[k] = x[base + k * 256];
#pragma unroll
    for (int k = 0; k < 4; k++) nv[k] = nz[base + k * 256];

#pragma unroll
    for (int k = 0; k < 4; k++) {
        float4 ov, lv;
        ov.x = xv[k].x + nv[k].x;  lv.x = lut_interp(ov.x, lut);
        ov.y = xv[k].y + nv[k].y;  lv.y = lut_interp(ov.y, lut);
        ov.z = xv[k].z + nv[k].z;  lv.z = lut_interp(ov.z, lut);
        ov.w = xv[k].w + nv[k].w;  lv.w = lut_interp(ov.w, lut);
        out[base + k * 256]      = ov;   // outputs = x + noise
        out[N4 + base + k * 256] = lv;   // likelihood
    }
}

extern "C" void kernel_launch(void* const* d_in, const int* in_sizes, int n_in,
                              void* d_out, int out_size)
{
    const float* x  = (const float*)d_in[0];
    const float* nz = (const float*)d_in[1];
    const float *m[5], *b[5], *f[4];

    // Two possible metadata orders:
    //  signature order:  x, noise, m0..m4, b0..b4, f0..f3  -> in_sizes[3]=1728 (m1)
    //  dict order:       x, noise, m0,b0,f0, m1,b1,f1, ...  -> in_sizes[3]=576  (b0)
    if (n_in >= 16 && in_sizes[3] == 1728) {
        for (int i = 0; i < 5; i++) m[i] = (const float*)d_in[2 + i];
        for (int i = 0; i < 5; i++) b[i] = (const float*)d_in[7 + i];
        for (int i = 0; i < 4; i++) f[i] = (const float*)d_in[12 + i];
    } else {
        int idx = 2;
        for (int i = 0; i < 5; i++) {
            m[i] = (const float*)d_in[idx++];
            b[i] = (const float*)d_in[idx++];
            if (i < 4) f[i] = (const float*)d_in[idx++];
        }
    }

    dim3 bgrid(LUT_N / 256, NCH);
    build_kernel<<<bgrid, 256>>>(m[0], m[1], m[2], m[3], m[4],
                                 b[0], b[1], b[2], b[3], b[4],
                                 f[0], f[1], f[2], f[3]);
    eb_main<<<3072, 256>>>((const float4*)x, (const float4*)nz, (float4*)d_out);
}